// round 1
// baseline (speedup 1.0000x reference)
#include <cuda_runtime.h>

typedef unsigned long long u64;

// ---- packed f32x2 helpers (Blackwell sm_103a) ----
__device__ __forceinline__ u64 pk2(float a, float b) {
    u64 r; asm("mov.b64 %0,{%1,%2};" : "=l"(r) : "f"(a), "f"(b)); return r;
}
__device__ __forceinline__ void fma2(u64 &d, u64 a, u64 b) {
    asm("fma.rn.f32x2 %0,%1,%2,%0;" : "+l"(d) : "l"(a), "l"(b));
}
__device__ __forceinline__ u64 add2(u64 a, u64 b) {
    u64 r; asm("add.rn.f32x2 %0,%1,%2;" : "=l"(r) : "l"(a), "l"(b)); return r;
}
__device__ __forceinline__ void up2(u64 v, float &x, float &y) {
    asm("mov.b64 {%0,%1},%2;" : "=f"(x), "=f"(y) : "l"(v));
}

// Shapes (fixed by the problem):
// x:(64,4,2,256,256)  w:(4,4,128,128,16,2)  bias:(4,128,128,2)  out:(64,4,2,128,128)
#define NCHUNK 4
#define NPC (64 / NCHUNK)   // n iterations per thread

// Thread = (x-pos, y-pos, c).  Warp lane = c*8 + dy (8 consecutive y per c-group).
// Block = 256 threads = 8 warps = 64 y positions x 4 c, fixed x position.
// Grid  = 128 (x) * 2 (y-tile) * NCHUNK.
__global__ void __launch_bounds__(256, 1) ttn_kernel(
    const float* __restrict__ X, const float* __restrict__ W,
    const float* __restrict__ B, float* __restrict__ O)
{
    __shared__ float4 smw[2048];   // 32 KB staging for one c-slice of weights

    const int tid  = threadIdx.x;
    const int warp = tid >> 5;
    const int lane = tid & 31;
    const int c    = lane >> 3;
    const int dy   = lane & 7;

    const int bid = blockIdx.x;
    const int nch = bid >> 8;         // n-chunk
    const int rem = bid & 255;
    const int xp  = rem >> 1;         // x position (0..127)
    const int y0  = (rem & 1) * 64;   // y tile base
    const int yl  = warp * 8 + dy;    // local y (0..63)
    const int y   = y0 + yl;

    // ---- stage weights gmem -> smem (coalesced) -> registers (swizzled, conflict-free) ----
    // w2[p*16+q] = packed (o0,o1) weight pair for this thread's (c, xp, y, p, q)
    u64 w2[64];
    for (int r = 0; r < 4; ++r) {
        __syncthreads();
#pragma unroll
        for (int i = 0; i < 8; ++i) {
            int G  = i * 256 + tid;        // float4 index within c-slice (0..2047)
            int p  = G >> 9;
            int yy = (G >> 3) & 63;
            int j  = G & 7;
            float4 v = __ldg((const float4*)W +
                             (((r * 4 + p) * 16384 + xp * 128 + y0 + yy) * 8 + j));
            smw[p * 512 + yy * 8 + (j ^ (yy & 7))] = v;
        }
        __syncthreads();
        if (c == r) {
#pragma unroll
            for (int p = 0; p < 4; ++p)
#pragma unroll
                for (int t = 0; t < 8; ++t) {
                    float4 v = smw[p * 512 + yl * 8 + (t ^ dy)];
                    w2[p * 16 + 2 * t]     = pk2(v.x, v.y);
                    w2[p * 16 + 2 * t + 1] = pk2(v.z, v.w);
                }
        }
    }

    // bias pair for the p this lane will write (p == c)
    const float2 bz = *(const float2*)(B + ((c * 128 + xp) * 128 + y) * 2);

    // x addressing: x[n][c][i][row][col], row in {2xp,2xp+1}, col base 2y
    const int n0    = nch * NPC;
    const int NSTR  = 4 * 2 * 65536;                      // per-n stride in x
    const int xbase = (n0 * 4 + c) * 131072 + (2 * xp) * 256 + 2 * y;
    const int OSTR  = 4 * 2 * 16384;                      // per-n stride in out
    int obase = ((n0 * 4 + c) * 2) * 16384 + xp * 128 + y; // p == c baked in

    // ---- 2-deep prefetch of the four float2 corner loads ----
    float2 v0[4], v1[4];
    {
        const float* p0 = X + xbase;
        v0[0] = *(const float2*)(p0);
        v0[1] = *(const float2*)(p0 + 256);
        v0[2] = *(const float2*)(p0 + 65536);
        v0[3] = *(const float2*)(p0 + 65536 + 256);
        const float* p1 = p0 + NSTR;
        v1[0] = *(const float2*)(p1);
        v1[1] = *(const float2*)(p1 + 256);
        v1[2] = *(const float2*)(p1 + 65536);
        v1[3] = *(const float2*)(p1 + 65536 + 256);
    }

#pragma unroll 2
    for (int it = 0; it < NPC; ++it) {
        float2 c0, c1, c2, c3;
        if ((it & 1) == 0) { c0 = v0[0]; c1 = v0[1]; c2 = v0[2]; c3 = v0[3]; }
        else               { c0 = v1[0]; c1 = v1[1]; c2 = v1[2]; c3 = v1[3]; }

        if (it + 2 < NPC) {
            const float* pn = X + xbase + (it + 2) * NSTR;
            float2 t0 = *(const float2*)(pn);
            float2 t1 = *(const float2*)(pn + 256);
            float2 t2 = *(const float2*)(pn + 65536);
            float2 t3 = *(const float2*)(pn + 65536 + 256);
            if ((it & 1) == 0) { v0[0] = t0; v0[1] = t1; v0[2] = t2; v0[3] = t3; }
            else               { v1[0] = t0; v1[1] = t1; v1[2] = t2; v1[3] = t3; }
        }

        // corners: a=(2x,2y) b=(2x+1,2y) e=(2x,2y+1) f=(2x+1,2y+1); index = d
        const float a0 = c0.x, e0 = c0.y, b0 = c1.x, f0 = c1.y;
        const float a1 = c2.x, e1 = c2.y, b1 = c3.x, f1 = c3.y;

        // patch[q], q = i*8 + j*4 + k*2 + l = a_i*b_j*e_k*f_l
        float ab[4] = { a0 * b0, a0 * b1, a1 * b0, a1 * b1 };   // g = i*2+j
        float ef[4] = { e0 * f0, e0 * f1, e1 * f0, e1 * f1 };   // m = k*2+l

        u64 acc[4] = { 0, 0, 0, 0 };   // per-p accumulator, packed over o
#pragma unroll
        for (int g = 0; g < 4; ++g)
#pragma unroll
            for (int m = 0; m < 4; ++m) {
                float pv = ab[g] * ef[m];
                u64 p2 = pk2(pv, pv);
                int q = g * 4 + m;
                fma2(acc[0], w2[q],      p2);
                fma2(acc[1], w2[16 + q], p2);
                fma2(acc[2], w2[32 + q], p2);
                fma2(acc[3], w2[48 + q], p2);
            }

        // reduce over c: lanes c*8+dy, butterfly xor 8 then xor 16
#pragma unroll
        for (int p = 0; p < 4; ++p) {
            acc[p] = add2(acc[p], __shfl_xor_sync(0xffffffffu, acc[p], 8));
            acc[p] = add2(acc[p], __shfl_xor_sync(0xffffffffu, acc[p], 16));
        }

        // lane with c-index writes p = c
        u64 val = acc[0];
        if (c == 1) val = acc[1];
        if (c == 2) val = acc[2];
        if (c == 3) val = acc[3];

        float r0, r1; up2(val, r0, r1);
        int oo = obase + it * OSTR;
        O[oo]          = r0 + bz.x;
        O[oo + 16384]  = r1 + bz.y;
    }
}

extern "C" void kernel_launch(void* const* d_in, const int* in_sizes, int n_in,
                              void* d_out, int out_size)
{
    const float* X = (const float*)d_in[0];   // x        (64,4,2,256,256)
    const float* W = (const float*)d_in[1];   // tensors  (4,4,128,128,2,2,2,2,2)
    const float* B = (const float*)d_in[2];   // bias     (4,128,128,2)
    float* O = (float*)d_out;                 // out      (64,4,2,128,128)
    (void)in_sizes; (void)n_in; (void)out_size;
    ttn_kernel<<<256 * NCHUNK, 256>>>(X, W, B, O);
}

// round 2
// speedup vs baseline: 1.0690x; 1.0690x over previous
#include <cuda_runtime.h>

typedef unsigned long long u64;

// ---- packed f32x2 helpers (Blackwell sm_103a) ----
__device__ __forceinline__ u64 pk2(float a, float b) {
    u64 r; asm("mov.b64 %0,{%1,%2};" : "=l"(r) : "f"(a), "f"(b)); return r;
}
__device__ __forceinline__ void fma2(u64 &d, u64 a, u64 b) {
    asm("fma.rn.f32x2 %0,%1,%2,%0;" : "+l"(d) : "l"(a), "l"(b));
}
__device__ __forceinline__ u64 mul2(u64 a, u64 b) {
    u64 r; asm("mul.rn.f32x2 %0,%1,%2;" : "=l"(r) : "l"(a), "l"(b)); return r;
}
__device__ __forceinline__ u64 add2(u64 a, u64 b) {
    u64 r; asm("add.rn.f32x2 %0,%1,%2;" : "=l"(r) : "l"(a), "l"(b)); return r;
}
__device__ __forceinline__ void up2(u64 v, float &x, float &y) {
    asm("mov.b64 {%0,%1},%2;" : "=f"(x), "=f"(y) : "l"(v));
}

// Shapes (fixed by the problem):
// x:(64,4,2,256,256)  w:(4,4,128,128,16,2)  bias:(4,128,128,2)  out:(64,4,2,128,128)
#define NCHUNK 4
#define NPC (64 / NCHUNK)   // n iterations per thread

// Block = 512 threads = 16 warps.
//   warps 0-7  (ph=0) own p in {0,1}
//   warps 8-15 (ph=1) own p in {2,3}
// Within each 8-warp group: warp wg covers 8 y positions, lane = c*8 + dy.
// Block geometry: fixed x position, 64-wide y tile, all 4 c, all 4 p.
// Grid = 128 (x) * 2 (y-tile) * NCHUNK.
__global__ void __launch_bounds__(512, 1) ttn_kernel(
    const float* __restrict__ X, const float* __restrict__ W,
    const float* __restrict__ B, float* __restrict__ O)
{
    __shared__ float4 smw[2048];   // 32 KB staging for one c-slice of weights

    const int tid  = threadIdx.x;
    const int warp = tid >> 5;
    const int lane = tid & 31;
    const int c    = lane >> 3;
    const int dy   = lane & 7;
    const int ph   = warp >> 3;       // p half: 0 -> p{0,1}, 1 -> p{2,3}
    const int wg   = warp & 7;        // warp within group

    const int bid = blockIdx.x;
    const int nch = bid >> 8;         // n-chunk
    const int rem = bid & 255;
    const int xp  = rem >> 1;         // x position (0..127)
    const int y0  = (rem & 1) * 64;   // y tile base
    const int yl  = wg * 8 + dy;      // local y (0..63)
    const int y   = y0 + yl;

    // ---- stage weights gmem -> smem (coalesced) -> registers (swizzled, conflict-free) ----
    // w2[pp*16+q] = packed (o0,o1) weight pair for this thread's (c, xp, y, p=2*ph+pp, q)
    u64 w2[32];
    for (int r = 0; r < 4; ++r) {
        __syncthreads();
#pragma unroll
        for (int i = 0; i < 4; ++i) {
            int G  = i * 512 + tid;        // float4 index within c-slice (0..2047)
            int p  = G >> 9;
            int yy = (G >> 3) & 63;
            int j  = G & 7;
            float4 v = __ldg((const float4*)W +
                             (((r * 4 + p) * 16384 + xp * 128 + y0 + yy) * 8 + j));
            smw[p * 512 + yy * 8 + (j ^ (yy & 7))] = v;
        }
        __syncthreads();
        if (c == r) {
#pragma unroll
            for (int pp = 0; pp < 2; ++pp) {
                int p = 2 * ph + pp;
#pragma unroll
                for (int t = 0; t < 8; ++t) {
                    float4 v = smw[p * 512 + yl * 8 + (t ^ dy)];
                    w2[pp * 16 + 2 * t]     = pk2(v.x, v.y);
                    w2[pp * 16 + 2 * t + 1] = pk2(v.z, v.w);
                }
            }
        }
    }

    // bias pair for the p this lane may write (p == 2*ph + c, valid only for c<2;
    // for c>=2 load a harmless valid address)
    const int pw = 2 * ph + (c & 1);
    const float2 bz = *(const float2*)(B + ((pw * 128 + xp) * 128 + y) * 2);

    // x addressing: x[n][c][i][row][col], row in {2xp,2xp+1}, col base 2y
    const int n0    = nch * NPC;
    const int NSTR  = 4 * 2 * 65536;                      // per-n stride in x
    const int xbase = (n0 * 4 + c) * 131072 + (2 * xp) * 256 + 2 * y;
    const int OSTR  = 4 * 2 * 16384;                      // per-n stride in out
    const int obase = ((n0 * 4 + pw) * 2) * 16384 + xp * 128 + y;

    // ---- 2-deep prefetch of the four float2 corner loads ----
    float2 v0[4], v1[4];
    {
        const float* p0 = X + xbase;
        v0[0] = *(const float2*)(p0);
        v0[1] = *(const float2*)(p0 + 256);
        v0[2] = *(const float2*)(p0 + 65536);
        v0[3] = *(const float2*)(p0 + 65536 + 256);
        const float* p1 = p0 + NSTR;
        v1[0] = *(const float2*)(p1);
        v1[1] = *(const float2*)(p1 + 256);
        v1[2] = *(const float2*)(p1 + 65536);
        v1[3] = *(const float2*)(p1 + 65536 + 256);
    }

#pragma unroll 2
    for (int it = 0; it < NPC; ++it) {
        float2 c0, c1, c2, c3;
        if ((it & 1) == 0) { c0 = v0[0]; c1 = v0[1]; c2 = v0[2]; c3 = v0[3]; }
        else               { c0 = v1[0]; c1 = v1[1]; c2 = v1[2]; c3 = v1[3]; }

        if (it + 2 < NPC) {
            const float* pn = X + xbase + (it + 2) * NSTR;
            float2 t0 = *(const float2*)(pn);
            float2 t1 = *(const float2*)(pn + 256);
            float2 t2 = *(const float2*)(pn + 65536);
            float2 t3 = *(const float2*)(pn + 65536 + 256);
            if ((it & 1) == 0) { v0[0] = t0; v0[1] = t1; v0[2] = t2; v0[3] = t3; }
            else               { v1[0] = t0; v1[1] = t1; v1[2] = t2; v1[3] = t3; }
        }

        // corners: a=(2x,2y) b=(2x+1,2y) e=(2x,2y+1) f=(2x+1,2y+1); index = d
        const float a0 = c0.x, e0 = c0.y, b0 = c1.x, f0 = c1.y;
        const float a1 = c2.x, e1 = c2.y, b1 = c3.x, f1 = c3.y;

        // patch[q], q = i*8 + j*4 + k*2 + l = a_i*b_j*e_k*f_l
        float ab[4] = { a0 * b0, a0 * b1, a1 * b0, a1 * b1 };   // g = i*2+j
        float ef[4] = { e0 * f0, e0 * f1, e1 * f0, e1 * f1 };   // m = k*2+l
        u64 ab2[4], ef2[4];
#pragma unroll
        for (int g = 0; g < 4; ++g) { ab2[g] = pk2(ab[g], ab[g]); ef2[g] = pk2(ef[g], ef[g]); }

        u64 acc0 = 0, acc1 = 0;   // accumulators for p = 2*ph+0 and 2*ph+1, packed over o
#pragma unroll
        for (int g = 0; g < 4; ++g)
#pragma unroll
            for (int m = 0; m < 4; ++m) {
                u64 p2 = mul2(ab2[g], ef2[m]);
                int q = g * 4 + m;
                fma2(acc0, w2[q],      p2);
                fma2(acc1, w2[16 + q], p2);
            }

        // reduce over c: lanes c*8+dy, butterfly xor 8 then xor 16
        acc0 = add2(acc0, __shfl_xor_sync(0xffffffffu, acc0, 8));
        acc1 = add2(acc1, __shfl_xor_sync(0xffffffffu, acc1, 8));
        acc0 = add2(acc0, __shfl_xor_sync(0xffffffffu, acc0, 16));
        acc1 = add2(acc1, __shfl_xor_sync(0xffffffffu, acc1, 16));

        // lanes with c==0 write p=2*ph, c==1 write p=2*ph+1
        if (c < 2) {
            u64 val = (c == 0) ? acc0 : acc1;
            float r0, r1; up2(val, r0, r1);
            int oo = obase + it * OSTR;
            O[oo]          = r0 + bz.x;
            O[oo + 16384]  = r1 + bz.y;
        }
    }
}

extern "C" void kernel_launch(void* const* d_in, const int* in_sizes, int n_in,
                              void* d_out, int out_size)
{
    const float* X = (const float*)d_in[0];   // x        (64,4,2,256,256)
    const float* W = (const float*)d_in[1];   // tensors  (4,4,128,128,2,2,2,2,2)
    const float* B = (const float*)d_in[2];   // bias     (4,128,128,2)
    float* O = (float*)d_out;                 // out      (64,4,2,128,128)
    (void)in_sizes; (void)n_in; (void)out_size;
    ttn_kernel<<<256 * NCHUNK, 512>>>(X, W, B, O);
}

// round 3
// speedup vs baseline: 1.0943x; 1.0237x over previous
#include <cuda_runtime.h>

typedef unsigned long long u64;

// ---- packed f32x2 helpers (Blackwell sm_103a) ----
__device__ __forceinline__ u64 pk2(float a, float b) {
    u64 r; asm("mov.b64 %0,{%1,%2};" : "=l"(r) : "f"(a), "f"(b)); return r;
}
__device__ __forceinline__ void fma2(u64 &d, u64 a, u64 b) {
    asm("fma.rn.f32x2 %0,%1,%2,%0;" : "+l"(d) : "l"(a), "l"(b));
}
__device__ __forceinline__ u64 mul2(u64 a, u64 b) {
    u64 r; asm("mul.rn.f32x2 %0,%1,%2;" : "=l"(r) : "l"(a), "l"(b)); return r;
}
__device__ __forceinline__ u64 add2(u64 a, u64 b) {
    u64 r; asm("add.rn.f32x2 %0,%1,%2;" : "=l"(r) : "l"(a), "l"(b)); return r;
}
__device__ __forceinline__ void up2(u64 v, float &x, float &y) {
    asm("mov.b64 {%0,%1},%2;" : "=f"(x), "=f"(y) : "l"(v));
}
__device__ __forceinline__ float2 ldcs2(const float2* p) {
    float2 v; asm("ld.global.cs.v2.f32 {%0,%1},[%2];" : "=f"(v.x), "=f"(v.y) : "l"(p)); return v;
}

// Shapes: x:(64,4,2,256,256) w:(4,4,128,128,16,2) bias:(4,128,128,2) out:(64,4,2,128,128)
#define NCHUNK 4
#define NPC (64 / NCHUNK)

// Block = 512 threads = 16 warps: warps 0-7 (ph=0) own p{0,1}, warps 8-15 (ph=1) own p{2,3}.
// lane = c*8 + dy; warp-in-group wg covers y = wg*8+dy. Block: fixed x, 64-y tile.
// x is staged cooperatively through SMEM (triple buffer) with a 2-deep gmem reg prefetch.
#define XBUF 1056              // float2 per x buffer: 4c * 2i * 2r * 66(pad)
__global__ void __launch_bounds__(512, 1) ttn_kernel(
    const float* __restrict__ X, const float* __restrict__ W,
    const float* __restrict__ B, float* __restrict__ O)
{
    __shared__ __align__(16) char sraw[32768];   // weight staging, then 3 x-buffers
    float4* smw = (float4*)sraw;
    float2* xsm = (float2*)sraw;

    const int tid  = threadIdx.x;
    const int warp = tid >> 5;
    const int lane = tid & 31;
    const int c    = lane >> 3;
    const int dy   = lane & 7;
    const int ph   = warp >> 3;
    const int wg   = warp & 7;

    const int bid = blockIdx.x;
    const int nch = bid >> 8;
    const int rem = bid & 255;
    const int xp  = rem >> 1;
    const int y0  = (rem & 1) * 64;
    const int yl  = wg * 8 + dy;
    const int y   = y0 + yl;
    const int n0  = nch * NPC;

    // ---- x staging thread roles: F0 = tid, F1 = tid + 512 (1024 float2 per slice) ----
    // plane = F>>6 -> (c_,i_,r_), yy = F&63
    const int F0 = tid, F1 = tid + 512;
    const int pl0 = F0 >> 6, yy0 = F0 & 63;
    const int pl1 = F1 >> 6, yy1 = F1 & 63;
    const int c0_ = pl0 >> 2, i0_ = (pl0 >> 1) & 1, r0_ = pl0 & 1;
    const int c1_ = pl1 >> 2, i1_ = (pl1 >> 1) & 1, r1_ = pl1 & 1;
    const float2* Xf2 = (const float2*)X;
    // gmem float2 offsets (n term added per slice); n-stride = 4*2*32768 = 262144
    const int goff0 = ((c0_ * 2 + i0_) * 32768) + (2 * xp + r0_) * 128 + y0 + yy0;
    const int goff1 = ((c1_ * 2 + i1_) * 32768) + (2 * xp + r1_) * 128 + y0 + yy1;
    // smem float2 offsets within a buffer
    const int soff0 = ((c0_ * 2 + i0_) * 2 + r0_) * 66 + yy0;
    const int soff1 = ((c1_ * 2 + i1_) * 2 + r1_) * 66 + yy1;

    // issue gmem prefetch of slices 0 and 1 NOW (hidden behind weight staging)
    float2 g[2][2];
    g[0][0] = ldcs2(Xf2 + (long)(n0 + 0) * 262144 + goff0);
    g[0][1] = ldcs2(Xf2 + (long)(n0 + 0) * 262144 + goff1);
    g[1][0] = ldcs2(Xf2 + (long)(n0 + 1) * 262144 + goff0);
    g[1][1] = ldcs2(Xf2 + (long)(n0 + 1) * 262144 + goff1);

    // ---- stage weights gmem -> smem (coalesced) -> registers (swizzled) ----
    u64 w2[32];
    for (int r = 0; r < 4; ++r) {
        __syncthreads();
#pragma unroll
        for (int i = 0; i < 4; ++i) {
            int G  = i * 512 + tid;
            int p  = G >> 9;
            int yy = (G >> 3) & 63;
            int j  = G & 7;
            float4 v = __ldg((const float4*)W +
                             (((r * 4 + p) * 16384 + xp * 128 + y0 + yy) * 8 + j));
            smw[p * 512 + yy * 8 + (j ^ (yy & 7))] = v;
        }
        __syncthreads();
        if (c == r) {
#pragma unroll
            for (int pp = 0; pp < 2; ++pp) {
                int p = 2 * ph + pp;
#pragma unroll
                for (int t = 0; t < 8; ++t) {
                    float4 v = smw[p * 512 + yl * 8 + (t ^ dy)];
                    w2[pp * 16 + 2 * t]     = pk2(v.x, v.y);
                    w2[pp * 16 + 2 * t + 1] = pk2(v.z, v.w);
                }
            }
        }
    }
    __syncthreads();   // weight buffer dead; x buffers may now overwrite it

    const int pw = 2 * ph + (c & 1);
    const float2 bz = *(const float2*)(B + ((pw * 128 + xp) * 128 + y) * 2);

    const int OSTR  = 4 * 2 * 16384;
    const int obase = ((n0 * 4 + pw) * 2) * 16384 + xp * 128 + y;
    const int xb    = c * 264 + yl;   // compute-side smem base (float2 units)

    // publish slice 0
    xsm[0 * XBUF + soff0] = g[0][0];
    xsm[0 * XBUF + soff1] = g[0][1];
    __syncthreads();

#pragma unroll
    for (int it = 0; it < NPC; ++it) {
        // gmem prefetch slice it+2 into slot it&1
        if (it + 2 < NPC) {
            g[it & 1][0] = ldcs2(Xf2 + (long)(n0 + it + 2) * 262144 + goff0);
            g[it & 1][1] = ldcs2(Xf2 + (long)(n0 + it + 2) * 262144 + goff1);
        }
        // publish slice it+1 into buffer (it+1)%3
        if (it + 1 < NPC) {
            int b = (it + 1) % 3;
            xsm[b * XBUF + soff0] = g[(it + 1) & 1][0];
            xsm[b * XBUF + soff1] = g[(it + 1) & 1][1];
        }

        // consume slice it from buffer it%3 (conflict-free LDS.64)
        const float2* xbuf = xsm + (it % 3) * XBUF + xb;
        float2 c0v = xbuf[0];     // (a0,e0)
        float2 c1v = xbuf[66];    // (b0,f0)
        float2 c2v = xbuf[132];   // (a1,e1)
        float2 c3v = xbuf[198];   // (b1,f1)

        const float a0 = c0v.x, e0 = c0v.y, b0 = c1v.x, f0 = c1v.y;
        const float a1 = c2v.x, e1 = c2v.y, b1 = c3v.x, f1 = c3v.y;

        u64 ab2[4] = { pk2(a0*b0, a0*b0), pk2(a0*b1, a0*b1),
                       pk2(a1*b0, a1*b0), pk2(a1*b1, a1*b1) };
        u64 ef2[4] = { pk2(e0*f0, e0*f0), pk2(e0*f1, e0*f1),
                       pk2(e1*f0, e1*f0), pk2(e1*f1, e1*f1) };

        // factored: acc_p = sum_g ab[g] * (sum_m w[g*4+m] * ef[m])
        u64 acc0, acc1;
#pragma unroll
        for (int gq = 0; gq < 4; ++gq) {
            u64 t0 = mul2(w2[gq * 4 + 0], ef2[0]);
            fma2(t0, w2[gq * 4 + 1], ef2[1]);
            fma2(t0, w2[gq * 4 + 2], ef2[2]);
            fma2(t0, w2[gq * 4 + 3], ef2[3]);
            u64 t1 = mul2(w2[16 + gq * 4 + 0], ef2[0]);
            fma2(t1, w2[16 + gq * 4 + 1], ef2[1]);
            fma2(t1, w2[16 + gq * 4 + 2], ef2[2]);
            fma2(t1, w2[16 + gq * 4 + 3], ef2[3]);
            if (gq == 0) { acc0 = mul2(ab2[0], t0); acc1 = mul2(ab2[0], t1); }
            else         { fma2(acc0, ab2[gq], t0); fma2(acc1, ab2[gq], t1); }
        }

        // reduce over c: butterfly xor 8 then xor 16
        acc0 = add2(acc0, __shfl_xor_sync(0xffffffffu, acc0, 8));
        acc1 = add2(acc1, __shfl_xor_sync(0xffffffffu, acc1, 8));
        acc0 = add2(acc0, __shfl_xor_sync(0xffffffffu, acc0, 16));
        acc1 = add2(acc1, __shfl_xor_sync(0xffffffffu, acc1, 16));

        if (c < 2) {
            u64 val = (c == 0) ? acc0 : acc1;
            float r0, r1; up2(val, r0, r1);
            int oo = obase + it * OSTR;
            O[oo]         = r0 + bz.x;
            O[oo + 16384] = r1 + bz.y;
        }
        __syncthreads();
    }
}

extern "C" void kernel_launch(void* const* d_in, const int* in_sizes, int n_in,
                              void* d_out, int out_size)
{
    const float* X = (const float*)d_in[0];   // x        (64,4,2,256,256)
    const float* W = (const float*)d_in[1];   // tensors  (4,4,128,128,2,2,2,2,2)
    const float* B = (const float*)d_in[2];   // bias     (4,128,128,2)
    float* O = (float*)d_out;                 // out      (64,4,2,128,128)
    (void)in_sizes; (void)n_in; (void)out_size;
    ttn_kernel<<<256 * NCHUNK, 512>>>(X, W, B, O);
}

// round 4
// speedup vs baseline: 1.1209x; 1.0243x over previous
#include <cuda_runtime.h>

typedef unsigned long long u64;

// ---- packed f32x2 helpers (Blackwell sm_103a) ----
__device__ __forceinline__ u64 pk2(float a, float b) {
    u64 r; asm("mov.b64 %0,{%1,%2};" : "=l"(r) : "f"(a), "f"(b)); return r;
}
__device__ __forceinline__ void fma2(u64 &d, u64 a, u64 b) {
    asm("fma.rn.f32x2 %0,%1,%2,%0;" : "+l"(d) : "l"(a), "l"(b));
}
__device__ __forceinline__ u64 mul2(u64 a, u64 b) {
    u64 r; asm("mul.rn.f32x2 %0,%1,%2;" : "=l"(r) : "l"(a), "l"(b)); return r;
}
__device__ __forceinline__ u64 add2(u64 a, u64 b) {
    u64 r; asm("add.rn.f32x2 %0,%1,%2;" : "=l"(r) : "l"(a), "l"(b)); return r;
}
__device__ __forceinline__ void up2(u64 v, float &x, float &y) {
    asm("mov.b64 {%0,%1},%2;" : "=f"(x), "=f"(y) : "l"(v));
}
__device__ __forceinline__ float2 ldcs2(const float2* p) {
    float2 v; asm("ld.global.cs.v2.f32 {%0,%1},[%2];" : "=f"(v.x), "=f"(v.y) : "l"(p)); return v;
}
__device__ __forceinline__ void cp8(unsigned sa, const float2* ga) {
    asm volatile("cp.async.ca.shared.global [%0],[%1],8;" :: "r"(sa), "l"(ga));
}
__device__ __forceinline__ void cp_commit() {
    asm volatile("cp.async.commit_group;");
}
__device__ __forceinline__ void cp_wait1() {
    asm volatile("cp.async.wait_group 1;");
}

// Shapes: x:(64,4,2,256,256) w:(4,4,128,128,16,2) bias:(4,128,128,2) out:(64,4,2,128,128)
#define NCHUNK 4
#define NPC (64 / NCHUNK)     // 16 n per block
#define XBUF 1024             // float2 per x buffer: 4c*2i*2r*64y, unpadded, XOR-swizzled

// Block = 512 threads = 16 warps: warps 0-7 (ph=0) own p{0,1}, warps 8-15 (ph=1) own p{2,3}.
// lane = c*8 + dy; warp-in-group wg covers y = wg*8+dy. Block: fixed x, 64-y tile.
// x pipelined via cp.async into a 4-buffer ring (32KB, aliased over weight staging);
// 2 n-slices consumed per barrier window.
__global__ void __launch_bounds__(512, 1) ttn_kernel(
    const float* __restrict__ X, const float* __restrict__ W,
    const float* __restrict__ B, float* __restrict__ O)
{
    __shared__ __align__(16) char sraw[32768];   // weight staging, then 4 x-buffers
    float4* smw = (float4*)sraw;
    float2* xsm = (float2*)sraw;

    const int tid  = threadIdx.x;
    const int warp = tid >> 5;
    const int lane = tid & 31;
    const int c    = lane >> 3;
    const int dy   = lane & 7;
    const int ph   = warp >> 3;
    const int wg   = warp & 7;

    const int bid = blockIdx.x;
    const int nch = bid >> 8;
    const int rem = bid & 255;
    const int xp  = rem >> 1;
    const int y0  = (rem & 1) * 64;
    const int yl  = wg * 8 + dy;
    const int y   = y0 + yl;
    const int n0  = nch * NPC;

    // ---- x staging roles: F0 = tid, F1 = tid + 512 (1024 float2 per slice) ----
    const int pl0 = tid >> 6, yy0 = tid & 63;
    const int c0_ = pl0 >> 2, i0_ = (pl0 >> 1) & 1, r0_ = pl0 & 1;
    const float2* Xf2 = (const float2*)X;
    const int goff0 = (c0_ * 2 + i0_) * 32768 + (2 * xp + r0_) * 128 + y0 + yy0;
    const int goff1 = goff0 + 131072;                      // c_ + 2
    const int soff0 = pl0 * 64 + (yy0 ^ (4 * c0_));        // XOR-4c swizzle
    const int soff1 = (pl0 + 8) * 64 + (yy0 ^ (4 * c0_) ^ 8);

    // reg prefetch of slices 0,1 (in flight during weight staging)
    float2 g00 = ldcs2(Xf2 + (long)(n0 + 0) * 262144 + goff0);
    float2 g01 = ldcs2(Xf2 + (long)(n0 + 0) * 262144 + goff1);
    float2 g10 = ldcs2(Xf2 + (long)(n0 + 1) * 262144 + goff0);
    float2 g11 = ldcs2(Xf2 + (long)(n0 + 1) * 262144 + goff1);

    // ---- stage weights gmem -> smem (coalesced) -> registers (swizzled) ----
    u64 w2[32];
    for (int r = 0; r < 4; ++r) {
        __syncthreads();
#pragma unroll
        for (int i = 0; i < 4; ++i) {
            int G  = i * 512 + tid;
            int p  = G >> 9;
            int yy = (G >> 3) & 63;
            int j  = G & 7;
            float4 v = __ldg((const float4*)W +
                             (((r * 4 + p) * 16384 + xp * 128 + y0 + yy) * 8 + j));
            smw[p * 512 + yy * 8 + (j ^ (yy & 7))] = v;
        }
        __syncthreads();
        if (c == r) {
#pragma unroll
            for (int pp = 0; pp < 2; ++pp) {
                int p = 2 * ph + pp;
#pragma unroll
                for (int t = 0; t < 8; ++t) {
                    float4 v = smw[p * 512 + yl * 8 + (t ^ dy)];
                    w2[pp * 16 + 2 * t]     = pk2(v.x, v.y);
                    w2[pp * 16 + 2 * t + 1] = pk2(v.z, v.w);
                }
            }
        }
    }
    __syncthreads();   // weight staging buffer dead; x ring may overwrite

    const int pw = 2 * ph + (c & 1);
    const float2 bz = *(const float2*)(B + ((pw * 128 + xp) * 128 + y) * 2);

    const int OSTR  = 4 * 2 * 16384;
    const int obase = ((n0 * 4 + pw) * 2) * 16384 + xp * 128 + y;
    const int ys    = yl ^ (4 * c);           // consumer swizzled y index
    const int xb    = c * 256 + ys;           // float2 base within a buffer

    // smem byte addresses for this thread's two cp.async targets (per buffer)
    unsigned sbase = (unsigned)__cvta_generic_to_shared(xsm);
    unsigned sa0   = sbase + soff0 * 8u;
    unsigned sa1   = sbase + soff1 * 8u;

    // publish slices 0,1; cp.async slices 2,3 into buffers 2,3
    xsm[0 * XBUF + soff0] = g00;  xsm[0 * XBUF + soff1] = g01;
    xsm[1 * XBUF + soff0] = g10;  xsm[1 * XBUF + soff1] = g11;
    cp8(sa0 + 2u * XBUF * 8u, Xf2 + (long)(n0 + 2) * 262144 + goff0);
    cp8(sa1 + 2u * XBUF * 8u, Xf2 + (long)(n0 + 2) * 262144 + goff1);
    cp8(sa0 + 3u * XBUF * 8u, Xf2 + (long)(n0 + 3) * 262144 + goff0);
    cp8(sa1 + 3u * XBUF * 8u, Xf2 + (long)(n0 + 3) * 262144 + goff1);
    cp_commit();       // G_pre = {2,3}
    __syncthreads();   // STS of slices 0,1 visible

#pragma unroll
    for (int w = 0; w < NPC / 2; ++w) {
        const int sA = 2 * w, sB = 2 * w + 1;
        const float2* bufA = xsm + (sA & 3) * XBUF + xb;
        const float2* bufB = xsm + (sB & 3) * XBUF + xb;

        // ---- consume two slices (independent chains) ----
        float2 A0 = bufA[0], A1 = bufA[64], A2 = bufA[128], A3 = bufA[192];
        float2 B0 = bufB[0], B1 = bufB[64], B2 = bufB[128], B3 = bufB[192];

        u64 accA0, accA1, accB0, accB1;
        {
            const float a0 = A0.x, e0 = A0.y, b0 = A1.x, f0 = A1.y;
            const float a1 = A2.x, e1 = A2.y, b1 = A3.x, f1 = A3.y;
            u64 ab2[4] = { pk2(a0*b0,a0*b0), pk2(a0*b1,a0*b1),
                           pk2(a1*b0,a1*b0), pk2(a1*b1,a1*b1) };
            u64 ef2[4] = { pk2(e0*f0,e0*f0), pk2(e0*f1,e0*f1),
                           pk2(e1*f0,e1*f0), pk2(e1*f1,e1*f1) };
#pragma unroll
            for (int gq = 0; gq < 4; ++gq) {
                u64 t0 = mul2(w2[gq*4+0], ef2[0]);
                fma2(t0, w2[gq*4+1], ef2[1]);
                fma2(t0, w2[gq*4+2], ef2[2]);
                fma2(t0, w2[gq*4+3], ef2[3]);
                u64 t1 = mul2(w2[16+gq*4+0], ef2[0]);
                fma2(t1, w2[16+gq*4+1], ef2[1]);
                fma2(t1, w2[16+gq*4+2], ef2[2]);
                fma2(t1, w2[16+gq*4+3], ef2[3]);
                if (gq == 0) { accA0 = mul2(ab2[0], t0); accA1 = mul2(ab2[0], t1); }
                else         { fma2(accA0, ab2[gq], t0); fma2(accA1, ab2[gq], t1); }
            }
        }
        {
            const float a0 = B0.x, e0 = B0.y, b0 = B1.x, f0 = B1.y;
            const float a1 = B2.x, e1 = B2.y, b1 = B3.x, f1 = B3.y;
            u64 ab2[4] = { pk2(a0*b0,a0*b0), pk2(a0*b1,a0*b1),
                           pk2(a1*b0,a1*b0), pk2(a1*b1,a1*b1) };
            u64 ef2[4] = { pk2(e0*f0,e0*f0), pk2(e0*f1,e0*f1),
                           pk2(e1*f0,e1*f0), pk2(e1*f1,e1*f1) };
#pragma unroll
            for (int gq = 0; gq < 4; ++gq) {
                u64 t0 = mul2(w2[gq*4+0], ef2[0]);
                fma2(t0, w2[gq*4+1], ef2[1]);
                fma2(t0, w2[gq*4+2], ef2[2]);
                fma2(t0, w2[gq*4+3], ef2[3]);
                u64 t1 = mul2(w2[16+gq*4+0], ef2[0]);
                fma2(t1, w2[16+gq*4+1], ef2[1]);
                fma2(t1, w2[16+gq*4+2], ef2[2]);
                fma2(t1, w2[16+gq*4+3], ef2[3]);
                if (gq == 0) { accB0 = mul2(ab2[0], t0); accB1 = mul2(ab2[0], t1); }
                else         { fma2(accB0, ab2[gq], t0); fma2(accB1, ab2[gq], t1); }
            }
        }

        // reduce over c (two independent butterfly pairs)
        accA0 = add2(accA0, __shfl_xor_sync(0xffffffffu, accA0, 8));
        accA1 = add2(accA1, __shfl_xor_sync(0xffffffffu, accA1, 8));
        accB0 = add2(accB0, __shfl_xor_sync(0xffffffffu, accB0, 8));
        accB1 = add2(accB1, __shfl_xor_sync(0xffffffffu, accB1, 8));
        accA0 = add2(accA0, __shfl_xor_sync(0xffffffffu, accA0, 16));
        accA1 = add2(accA1, __shfl_xor_sync(0xffffffffu, accA1, 16));
        accB0 = add2(accB0, __shfl_xor_sync(0xffffffffu, accB0, 16));
        accB1 = add2(accB1, __shfl_xor_sync(0xffffffffu, accB1, 16));

        if (c < 2) {
            u64 vA = (c == 0) ? accA0 : accA1;
            u64 vB = (c == 0) ? accB0 : accB1;
            float r0, r1; up2(vA, r0, r1);
            float s0, s1; up2(vB, s0, s1);
            int oA = obase + sA * OSTR;
            int oB = obase + sB * OSTR;
            O[oA]         = r0 + bz.x;
            O[oA + 16384] = r1 + bz.y;
            O[oB]         = s0 + bz.x;
            O[oB + 16384] = s1 + bz.y;
        }

        __syncthreads();   // all consumption of slices sA,sB done

        // refill: slices sA+4, sB+4 into the buffers just consumed
        if (w < NPC / 2 - 2) {
            cp8(sa0 + (unsigned)(sA & 3) * XBUF * 8u, Xf2 + (long)(n0 + sA + 4) * 262144 + goff0);
            cp8(sa1 + (unsigned)(sA & 3) * XBUF * 8u, Xf2 + (long)(n0 + sA + 4) * 262144 + goff1);
            cp8(sa0 + (unsigned)(sB & 3) * XBUF * 8u, Xf2 + (long)(n0 + sB + 4) * 262144 + goff0);
            cp8(sa1 + (unsigned)(sB & 3) * XBUF * 8u, Xf2 + (long)(n0 + sB + 4) * 262144 + goff1);
        }
        cp_commit();       // commit (possibly empty) group
        cp_wait1();        // previous group landed -> next window's slices ready
        __syncthreads();
    }
}

extern "C" void kernel_launch(void* const* d_in, const int* in_sizes, int n_in,
                              void* d_out, int out_size)
{
    const float* X = (const float*)d_in[0];   // x        (64,4,2,256,256)
    const float* W = (const float*)d_in[1];   // tensors  (4,4,128,128,2,2,2,2,2)
    const float* B = (const float*)d_in[2];   // bias     (4,128,128,2)
    float* O = (float*)d_out;                 // out      (64,4,2,128,128)
    (void)in_sizes; (void)n_in; (void)out_size;
    ttn_kernel<<<256 * NCHUNK, 512>>>(X, W, B, O);
}

// round 5
// speedup vs baseline: 1.3452x; 1.2001x over previous
#include <cuda_runtime.h>

typedef unsigned long long u64;

// ---- packed f32x2 helpers (Blackwell sm_103a) ----
__device__ __forceinline__ u64 pk2(float a, float b) {
    u64 r; asm("mov.b64 %0,{%1,%2};" : "=l"(r) : "f"(a), "f"(b)); return r;
}
__device__ __forceinline__ void fma2(u64 &d, u64 a, u64 b) {
    asm("fma.rn.f32x2 %0,%1,%2,%0;" : "+l"(d) : "l"(a), "l"(b));
}
__device__ __forceinline__ u64 mul2(u64 a, u64 b) {
    u64 r; asm("mul.rn.f32x2 %0,%1,%2;" : "=l"(r) : "l"(a), "l"(b)); return r;
}
__device__ __forceinline__ u64 add2(u64 a, u64 b) {
    u64 r; asm("add.rn.f32x2 %0,%1,%2;" : "=l"(r) : "l"(a), "l"(b)); return r;
}
__device__ __forceinline__ void up2(u64 v, float &x, float &y) {
    asm("mov.b64 {%0,%1},%2;" : "=f"(x), "=f"(y) : "l"(v));
}
__device__ __forceinline__ float2 ldcs2(const float2* p) {
    float2 v; asm("ld.global.cs.v2.f32 {%0,%1},[%2];" : "=f"(v.x), "=f"(v.y) : "l"(p)); return v;
}
__device__ __forceinline__ void cp8(unsigned sa, const float2* ga) {
    asm volatile("cp.async.ca.shared.global [%0],[%1],8;" :: "r"(sa), "l"(ga));
}
__device__ __forceinline__ void cp_commit() {
    asm volatile("cp.async.commit_group;");
}
__device__ __forceinline__ void cp_wait1() {
    asm volatile("cp.async.wait_group 1;");
}

// Shapes: x:(64,4,2,256,256) w:(4,4,128,128,16,2) bias:(4,128,128,2) out:(64,4,2,128,128)
#define NCHUNK 2
#define NPC (64 / NCHUNK)     // 32 n per block
#define XBUF 512              // float2 per x slice buffer: 4c*2i*2r*32y

// Block = 256 threads = 8 warps, 2 blocks/SM.
//   warps 0-3 (ph=0) own p{0,1}; warps 4-7 (ph=1) own p{2,3}
//   lane = c*8+dy; warp wgy covers y = wgy*8+dy (y-tile of 32). Fixed x position.
// Grid = 128 (x) * 4 (y-tile) * NCHUNK = 1024.
// x pipelined via cp.async 4-buffer ring (16KB, aliased over weight staging);
// 2 n-slices consumed per barrier window.
__global__ void __launch_bounds__(256, 2) ttn_kernel(
    const float* __restrict__ X, const float* __restrict__ W,
    const float* __restrict__ B, float* __restrict__ O)
{
    __shared__ __align__(16) char sraw[16384];   // weight staging, then 4 x-buffers
    float4* smw = (float4*)sraw;
    float2* xsm = (float2*)sraw;

    const int tid  = threadIdx.x;
    const int warp = tid >> 5;
    const int lane = tid & 31;
    const int c    = lane >> 3;
    const int dy   = lane & 7;
    const int ph   = warp >> 2;
    const int wgy  = warp & 3;

    const int bid = blockIdx.x;
    const int nch = bid >> 9;
    const int rem = bid & 511;
    const int xp  = rem >> 2;
    const int y0  = (rem & 3) * 32;
    const int yl  = wgy * 8 + dy;      // 0..31
    const int y   = y0 + yl;
    const int n0  = nch * NPC;

    // ---- x staging roles: F0 = tid, F1 = tid + 256 (512 float2 per slice) ----
    // plane = F>>5 -> (c_,i_,r_), yy = F&31
    const int pl0 = tid >> 5, yy0 = tid & 31;
    const int c0_ = pl0 >> 2, i0_ = (pl0 >> 1) & 1, r0_ = pl0 & 1;
    const float2* Xf2 = (const float2*)X;
    const int goff0 = (c0_ * 2 + i0_) * 32768 + (2 * xp + r0_) * 128 + y0 + yy0;
    const int goff1 = goff0 + 131072;                        // c_ + 2
    const int soff0 = pl0 * 32 + (yy0 ^ (4 * c0_));          // XOR-4c swizzle
    const int soff1 = (pl0 + 8) * 32 + (yy0 ^ (4 * c0_) ^ 8);

    // reg prefetch of slices 0,1 (in flight during weight staging)
    float2 g00 = ldcs2(Xf2 + (long)(n0 + 0) * 262144 + goff0);
    float2 g01 = ldcs2(Xf2 + (long)(n0 + 0) * 262144 + goff1);
    float2 g10 = ldcs2(Xf2 + (long)(n0 + 1) * 262144 + goff0);
    float2 g11 = ldcs2(Xf2 + (long)(n0 + 1) * 262144 + goff1);

    // ---- stage weights gmem -> smem (coalesced) -> registers (swizzled) ----
    u64 w2[32];
    for (int r = 0; r < 4; ++r) {
        __syncthreads();
#pragma unroll
        for (int i = 0; i < 4; ++i) {
            int G  = i * 256 + tid;        // float4 index within c-slice (0..1023)
            int p  = G >> 8;
            int yy = (G >> 3) & 31;
            int j  = G & 7;
            float4 v = __ldg((const float4*)W +
                             (((r * 4 + p) * 16384 + xp * 128 + y0 + yy) * 8 + j));
            smw[p * 256 + yy * 8 + (j ^ (yy & 7))] = v;
        }
        __syncthreads();
        if (c == r) {
#pragma unroll
            for (int pp = 0; pp < 2; ++pp) {
                int p = 2 * ph + pp;
#pragma unroll
                for (int t = 0; t < 8; ++t) {
                    float4 v = smw[p * 256 + yl * 8 + (t ^ dy)];
                    w2[pp * 16 + 2 * t]     = pk2(v.x, v.y);
                    w2[pp * 16 + 2 * t + 1] = pk2(v.z, v.w);
                }
            }
        }
    }
    __syncthreads();   // weight staging buffer dead; x ring may overwrite

    const int pw = 2 * ph + (c & 1);
    const float2 bz = *(const float2*)(B + ((pw * 128 + xp) * 128 + y) * 2);

    const int OSTR  = 4 * 2 * 16384;
    const int obase = ((n0 * 4 + pw) * 2) * 16384 + xp * 128 + y;
    const int xb    = c * 128 + (yl ^ (4 * c));   // float2 base within a buffer

    unsigned sbase = (unsigned)__cvta_generic_to_shared(xsm);
    unsigned sa0   = sbase + soff0 * 8u;
    unsigned sa1   = sbase + soff1 * 8u;

    // publish slices 0,1; cp.async slices 2,3 into buffers 2,3
    xsm[0 * XBUF + soff0] = g00;  xsm[0 * XBUF + soff1] = g01;
    xsm[1 * XBUF + soff0] = g10;  xsm[1 * XBUF + soff1] = g11;
    cp8(sa0 + 2u * XBUF * 8u, Xf2 + (long)(n0 + 2) * 262144 + goff0);
    cp8(sa1 + 2u * XBUF * 8u, Xf2 + (long)(n0 + 2) * 262144 + goff1);
    cp8(sa0 + 3u * XBUF * 8u, Xf2 + (long)(n0 + 3) * 262144 + goff0);
    cp8(sa1 + 3u * XBUF * 8u, Xf2 + (long)(n0 + 3) * 262144 + goff1);
    cp_commit();
    __syncthreads();

#pragma unroll 2
    for (int w = 0; w < NPC / 2; ++w) {
        const int sA = 2 * w, sB = 2 * w + 1;
        const float2* bufA = xsm + (sA & 3) * XBUF + xb;
        const float2* bufB = xsm + (sB & 3) * XBUF + xb;

        // ---- consume two slices (independent chains) ----
        float2 A0 = bufA[0], A1 = bufA[32], A2 = bufA[64], A3 = bufA[96];
        float2 B0 = bufB[0], B1 = bufB[32], B2 = bufB[64], B3 = bufB[96];

        u64 accA0, accA1, accB0, accB1;
        {
            const float a0 = A0.x, e0 = A0.y, b0 = A1.x, f0 = A1.y;
            const float a1 = A2.x, e1 = A2.y, b1 = A3.x, f1 = A3.y;
            u64 ab2[4] = { pk2(a0*b0,a0*b0), pk2(a0*b1,a0*b1),
                           pk2(a1*b0,a1*b0), pk2(a1*b1,a1*b1) };
            u64 ef2[4] = { pk2(e0*f0,e0*f0), pk2(e0*f1,e0*f1),
                           pk2(e1*f0,e1*f0), pk2(e1*f1,e1*f1) };
#pragma unroll
            for (int gq = 0; gq < 4; ++gq) {
                u64 t0 = mul2(w2[gq*4+0], ef2[0]);
                fma2(t0, w2[gq*4+1], ef2[1]);
                fma2(t0, w2[gq*4+2], ef2[2]);
                fma2(t0, w2[gq*4+3], ef2[3]);
                u64 t1 = mul2(w2[16+gq*4+0], ef2[0]);
                fma2(t1, w2[16+gq*4+1], ef2[1]);
                fma2(t1, w2[16+gq*4+2], ef2[2]);
                fma2(t1, w2[16+gq*4+3], ef2[3]);
                if (gq == 0) { accA0 = mul2(ab2[0], t0); accA1 = mul2(ab2[0], t1); }
                else         { fma2(accA0, ab2[gq], t0); fma2(accA1, ab2[gq], t1); }
            }
        }
        {
            const float a0 = B0.x, e0 = B0.y, b0 = B1.x, f0 = B1.y;
            const float a1 = B2.x, e1 = B2.y, b1 = B3.x, f1 = B3.y;
            u64 ab2[4] = { pk2(a0*b0,a0*b0), pk2(a0*b1,a0*b1),
                           pk2(a1*b0,a1*b0), pk2(a1*b1,a1*b1) };
            u64 ef2[4] = { pk2(e0*f0,e0*f0), pk2(e0*f1,e0*f1),
                           pk2(e1*f0,e1*f0), pk2(e1*f1,e1*f1) };
#pragma unroll
            for (int gq = 0; gq < 4; ++gq) {
                u64 t0 = mul2(w2[gq*4+0], ef2[0]);
                fma2(t0, w2[gq*4+1], ef2[1]);
                fma2(t0, w2[gq*4+2], ef2[2]);
                fma2(t0, w2[gq*4+3], ef2[3]);
                u64 t1 = mul2(w2[16+gq*4+0], ef2[0]);
                fma2(t1, w2[16+gq*4+1], ef2[1]);
                fma2(t1, w2[16+gq*4+2], ef2[2]);
                fma2(t1, w2[16+gq*4+3], ef2[3]);
                if (gq == 0) { accB0 = mul2(ab2[0], t0); accB1 = mul2(ab2[0], t1); }
                else         { fma2(accB0, ab2[gq], t0); fma2(accB1, ab2[gq], t1); }
            }
        }

        // reduce over c (two independent butterfly pairs)
        accA0 = add2(accA0, __shfl_xor_sync(0xffffffffu, accA0, 8));
        accA1 = add2(accA1, __shfl_xor_sync(0xffffffffu, accA1, 8));
        accB0 = add2(accB0, __shfl_xor_sync(0xffffffffu, accB0, 8));
        accB1 = add2(accB1, __shfl_xor_sync(0xffffffffu, accB1, 8));
        accA0 = add2(accA0, __shfl_xor_sync(0xffffffffu, accA0, 16));
        accA1 = add2(accA1, __shfl_xor_sync(0xffffffffu, accA1, 16));
        accB0 = add2(accB0, __shfl_xor_sync(0xffffffffu, accB0, 16));
        accB1 = add2(accB1, __shfl_xor_sync(0xffffffffu, accB1, 16));

        if (c < 2) {
            u64 vA = (c == 0) ? accA0 : accA1;
            u64 vB = (c == 0) ? accB0 : accB1;
            float r0, r1; up2(vA, r0, r1);
            float s0, s1; up2(vB, s0, s1);
            int oA = obase + sA * OSTR;
            int oB = obase + sB * OSTR;
            O[oA]         = r0 + bz.x;
            O[oA + 16384] = r1 + bz.y;
            O[oB]         = s0 + bz.x;
            O[oB + 16384] = s1 + bz.y;
        }

        __syncthreads();   // consumption of slices sA,sB done

        // refill: slices sA+4, sB+4 into the buffers just consumed
        if (w < NPC / 2 - 2) {
            cp8(sa0 + (unsigned)(sA & 3) * XBUF * 8u, Xf2 + (long)(n0 + sA + 4) * 262144 + goff0);
            cp8(sa1 + (unsigned)(sA & 3) * XBUF * 8u, Xf2 + (long)(n0 + sA + 4) * 262144 + goff1);
            cp8(sa0 + (unsigned)(sB & 3) * XBUF * 8u, Xf2 + (long)(n0 + sB + 4) * 262144 + goff0);
            cp8(sa1 + (unsigned)(sB & 3) * XBUF * 8u, Xf2 + (long)(n0 + sB + 4) * 262144 + goff1);
        }
        cp_commit();
        cp_wait1();        // group from previous window landed
        __syncthreads();
    }
}

extern "C" void kernel_launch(void* const* d_in, const int* in_sizes, int n_in,
                              void* d_out, int out_size)
{
    const float* X = (const float*)d_in[0];   // x        (64,4,2,256,256)
    const float* W = (const float*)d_in[1];   // tensors  (4,4,128,128,2,2,2,2,2)
    const float* B = (const float*)d_in[2];   // bias     (4,128,128,2)
    float* O = (float*)d_out;                 // out      (64,4,2,128,128)
    (void)in_sizes; (void)n_in; (void)out_size;
    ttn_kernel<<<128 * 4 * NCHUNK, 256>>>(X, W, B, O);
}

// round 6
// speedup vs baseline: 1.4731x; 1.0951x over previous
#include <cuda_runtime.h>

typedef unsigned long long u64;

// ---- packed f32x2 helpers (Blackwell sm_103a) ----
__device__ __forceinline__ u64 pk2(float a, float b) {
    u64 r; asm("mov.b64 %0,{%1,%2};" : "=l"(r) : "f"(a), "f"(b)); return r;
}
__device__ __forceinline__ void fma2(u64 &d, u64 a, u64 b) {
    asm("fma.rn.f32x2 %0,%1,%2,%0;" : "+l"(d) : "l"(a), "l"(b));
}
__device__ __forceinline__ u64 mul2(u64 a, u64 b) {
    u64 r; asm("mul.rn.f32x2 %0,%1,%2;" : "=l"(r) : "l"(a), "l"(b)); return r;
}
__device__ __forceinline__ u64 add2(u64 a, u64 b) {
    u64 r; asm("add.rn.f32x2 %0,%1,%2;" : "=l"(r) : "l"(a), "l"(b)); return r;
}
__device__ __forceinline__ void up2(u64 v, float &x, float &y) {
    asm("mov.b64 {%0,%1},%2;" : "=f"(x), "=f"(y) : "l"(v));
}
__device__ __forceinline__ void cp8(unsigned sa, const float2* ga) {
    asm volatile("cp.async.ca.shared.global [%0],[%1],8;" :: "r"(sa), "l"(ga));
}
__device__ __forceinline__ void cp_commit() {
    asm volatile("cp.async.commit_group;");
}
__device__ __forceinline__ void cp_wait2() {
    asm volatile("cp.async.wait_group 2;");
}

// Shapes: x:(64,4,2,256,256) w:(4,4,128,128,16,2) bias:(4,128,128,2) out:(64,4,2,128,128)
#define NCHUNK 2
#define NPC (64 / NCHUNK)     // 32 n per block
#define XBUF 256              // float2 per x slice: 16 planes (c,i,r) * 16 y

// Block = 128 threads = 4 warps, 4 blocks/SM (4 independent barrier domains).
//   warps 0-1 (ph=0) own p{0,1}; warps 2-3 (ph=1) own p{2,3}
//   lane = c*8+dy; wgy = warp&1 covers y = wgy*8+dy (y-tile of 16). Fixed x position.
// Grid = 128 (x) * 8 (y-tile) * NCHUNK = 2048.
// x pipelined via cp.async 4-buffer ring, depth 3, ONE sync per slice.
__global__ void __launch_bounds__(128, 4) ttn_kernel(
    const float* __restrict__ X, const float* __restrict__ W,
    const float* __restrict__ B, float* __restrict__ O)
{
    __shared__ __align__(16) float4 smw[512];          // 8 KB weight staging
    __shared__ __align__(16) float2 xsm[4 * XBUF];     // 8 KB x ring (separate!)

    const int tid  = threadIdx.x;
    const int warp = tid >> 5;
    const int lane = tid & 31;
    const int c    = lane >> 3;
    const int dy   = lane & 7;
    const int ph   = warp >> 1;
    const int wgy  = warp & 1;

    const int bid = blockIdx.x;
    const int nch = bid >> 10;
    const int rem = bid & 1023;
    const int xp  = rem >> 3;
    const int y0  = (rem & 7) * 16;
    const int yl  = wgy * 8 + dy;      // 0..15
    const int y   = y0 + yl;
    const int n0  = nch * NPC;

    // ---- x staging roles: F0 = tid, F1 = tid + 128 (256 float2 per slice) ----
    // plane = F>>4 -> (c_,i_,r_), yy = F&15; swizzle key(c) = 8*(c&1) | 4*(c>>1)
    const int pl0 = tid >> 4, yy0 = tid & 15;
    const int c0_ = pl0 >> 2, i0_ = (pl0 >> 1) & 1, r0_ = pl0 & 1;
    const int c1_ = c0_ + 2;
    const float2* Xf2 = (const float2*)X;
    const int goff0 = (c0_ * 2 + i0_) * 32768 + (2 * xp + r0_) * 128 + y0 + yy0;
    const int goff1 = goff0 + 131072;                        // c_ + 2
    const int key0  = 8 * (c0_ & 1) + 4 * (c0_ >> 1);
    const int key1  = 8 * (c1_ & 1) + 4 * (c1_ >> 1);
    const int soff0 = pl0 * 16 + (yy0 ^ key0);
    const int soff1 = (pl0 + 8) * 16 + (yy0 ^ key1);

    unsigned sbase = (unsigned)__cvta_generic_to_shared(xsm);
    unsigned sa0   = sbase + soff0 * 8u;
    unsigned sa1   = sbase + soff1 * 8u;

    // prologue: cp.async slices 0,1,2 (fully overlapped with weight staging)
#pragma unroll
    for (int s = 0; s < 3; ++s) {
        cp8(sa0 + (unsigned)s * XBUF * 8u, Xf2 + (long)(n0 + s) * 262144 + goff0);
        cp8(sa1 + (unsigned)s * XBUF * 8u, Xf2 + (long)(n0 + s) * 262144 + goff1);
        cp_commit();
    }

    // ---- stage weights gmem -> smem (coalesced) -> registers (swizzled) ----
    u64 w2[32];
    for (int r = 0; r < 4; ++r) {
        __syncthreads();
#pragma unroll
        for (int i = 0; i < 4; ++i) {
            int G  = i * 128 + tid;        // float4 index within c-slice (0..511)
            int p  = G >> 7;
            int yy = (G >> 3) & 15;
            int j  = G & 7;
            float4 v = __ldg((const float4*)W +
                             (((r * 4 + p) * 16384 + xp * 128 + y0 + yy) * 8 + j));
            smw[p * 128 + yy * 8 + (j ^ (yy & 7))] = v;
        }
        __syncthreads();
        if (c == r) {
#pragma unroll
            for (int pp = 0; pp < 2; ++pp) {
                int p = 2 * ph + pp;
#pragma unroll
                for (int t = 0; t < 8; ++t) {
                    float4 v = smw[p * 128 + yl * 8 + (t ^ dy)];
                    w2[pp * 16 + 2 * t]     = pk2(v.x, v.y);
                    w2[pp * 16 + 2 * t + 1] = pk2(v.z, v.w);
                }
            }
        }
    }

    const int pw = 2 * ph + (c & 1);
    const float2 bz = *(const float2*)(B + ((pw * 128 + xp) * 128 + y) * 2);

    const int OSTR  = 4 * 2 * 16384;
    const int obase = ((n0 * 4 + pw) * 2) * 16384 + xp * 128 + y;
    const int keyc  = 8 * (c & 1) + 4 * (c >> 1);
    const int xb    = c * 64 + (yl ^ keyc);   // float2 base within a buffer

#pragma unroll 4
    for (int s = 0; s < NPC; ++s) {
        cp_wait2();          // group for slice s has landed
        __syncthreads();     // visible to all; also retires last iter's reads

        const float2* buf = xsm + (s & 3) * XBUF + xb;
        float2 A0 = buf[0], A1 = buf[16], A2 = buf[32], A3 = buf[48];

        // refill slice s+3 into buffer (s+3)&3 (consumed in iter s-1)
        if (s + 3 < NPC) {
            cp8(sa0 + (unsigned)((s + 3) & 3) * XBUF * 8u,
                Xf2 + (long)(n0 + s + 3) * 262144 + goff0);
            cp8(sa1 + (unsigned)((s + 3) & 3) * XBUF * 8u,
                Xf2 + (long)(n0 + s + 3) * 262144 + goff1);
        }
        cp_commit();

        const float a0 = A0.x, e0 = A0.y, b0 = A1.x, f0 = A1.y;
        const float a1 = A2.x, e1 = A2.y, b1 = A3.x, f1 = A3.y;

        u64 ab2[4] = { pk2(a0*b0,a0*b0), pk2(a0*b1,a0*b1),
                       pk2(a1*b0,a1*b0), pk2(a1*b1,a1*b1) };
        u64 ef2[4] = { pk2(e0*f0,e0*f0), pk2(e0*f1,e0*f1),
                       pk2(e1*f0,e1*f0), pk2(e1*f1,e1*f1) };

        // factored: acc_p = sum_g ab[g] * (sum_m w[g*4+m] * ef[m])
        u64 acc0, acc1;
#pragma unroll
        for (int gq = 0; gq < 4; ++gq) {
            u64 t0 = mul2(w2[gq*4+0], ef2[0]);
            fma2(t0, w2[gq*4+1], ef2[1]);
            fma2(t0, w2[gq*4+2], ef2[2]);
            fma2(t0, w2[gq*4+3], ef2[3]);
            u64 t1 = mul2(w2[16+gq*4+0], ef2[0]);
            fma2(t1, w2[16+gq*4+1], ef2[1]);
            fma2(t1, w2[16+gq*4+2], ef2[2]);
            fma2(t1, w2[16+gq*4+3], ef2[3]);
            if (gq == 0) { acc0 = mul2(ab2[0], t0); acc1 = mul2(ab2[0], t1); }
            else         { fma2(acc0, ab2[gq], t0); fma2(acc1, ab2[gq], t1); }
        }

        // reduce over c: butterfly xor 8 then xor 16
        acc0 = add2(acc0, __shfl_xor_sync(0xffffffffu, acc0, 8));
        acc1 = add2(acc1, __shfl_xor_sync(0xffffffffu, acc1, 8));
        acc0 = add2(acc0, __shfl_xor_sync(0xffffffffu, acc0, 16));
        acc1 = add2(acc1, __shfl_xor_sync(0xffffffffu, acc1, 16));

        if (c < 2) {
            u64 val = (c == 0) ? acc0 : acc1;
            float r0, r1; up2(val, r0, r1);
            int oo = obase + s * OSTR;
            O[oo]         = r0 + bz.x;
            O[oo + 16384] = r1 + bz.y;
        }
    }
}

extern "C" void kernel_launch(void* const* d_in, const int* in_sizes, int n_in,
                              void* d_out, int out_size)
{
    const float* X = (const float*)d_in[0];   // x        (64,4,2,256,256)
    const float* W = (const float*)d_in[1];   // tensors  (4,4,128,128,2,2,2,2,2)
    const float* B = (const float*)d_in[2];   // bias     (4,128,128,2)
    float* O = (float*)d_out;                 // out      (64,4,2,128,128)
    (void)in_sizes; (void)n_in; (void)out_size;
    ttn_kernel<<<128 * 8 * NCHUNK, 128>>>(X, W, B, O);
}